// round 12
// baseline (speedup 1.0000x reference)
#include <cuda_runtime.h>
#include <cstdint>

#define D_IN   1024
#define DMODEL 1024
#define BB     4
#define NN     2048
#define NH     16
#define HD     64
#define MTOT   (BB*NN)   // 8192

// Scratch (device globals: allocation-free rule)
__device__ float g_xr[(size_t)MTOT*D_IN];        // X tf32, k-permuted per row
__device__ float g_wt[(size_t)4*DMODEL*D_IN];    // W^T tf32, k-permuted per col-row
__device__ float g_q[(size_t)BB*NH*NN*HD];       // tf32, scaled, d-permuted
__device__ float g_k[(size_t)BB*NH*NN*HD];       // tf32, d-permuted
__device__ float g_v[(size_t)BB*NH*HD*NN];       // tf32, TRANSPOSED [bh][d][n], n-permuted
__device__ float g_ctx[(size_t)MTOT*DMODEL];     // tf32, k-permuted per row

__device__ __forceinline__ float to_tf32(float x) {
    float r;
    asm("cvt.rna.tf32.f32 %0, %1;" : "=f"(r) : "f"(x));
    return r;
}

__device__ __forceinline__ void mma_tf32(float c[4], float a0, float a1, float a2, float a3,
                                         float b0, float b1) {
    asm("mma.sync.aligned.m16n8k8.row.col.f32.tf32.tf32.f32 "
        "{%0,%1,%2,%3},{%4,%5,%6,%7},{%8,%9},{%0,%1,%2,%3};"
        : "+f"(c[0]), "+f"(c[1]), "+f"(c[2]), "+f"(c[3])
        : "r"(__float_as_uint(a0)), "r"(__float_as_uint(a1)),
          "r"(__float_as_uint(a2)), "r"(__float_as_uint(a3)),
          "r"(__float_as_uint(b0)), "r"(__float_as_uint(b1)));
}

__device__ __forceinline__ void cp16(uint32_t s, const float* g) {
    asm volatile("cp.async.cg.shared.global [%0], [%1], 16;" :: "r"(s), "l"(g) : "memory");
}
#define CP_COMMIT() asm volatile("cp.async.commit_group;" ::: "memory")
#define CP_WAIT2()  asm volatile("cp.async.wait_group 2;" ::: "memory")
#define CP_WAIT0()  asm volatile("cp.async.wait_group 0;" ::: "memory")

// ---------------------------------------------------------------------------
// Prep. X: tf32 + k-within-16 permutation keyed by row&3. W: transpose to
// [n][k], tf32, same permutation keyed by n&3. All 4 weights in one launch.
// ---------------------------------------------------------------------------
__global__ __launch_bounds__(256)
void prep_x(const float* __restrict__ x)
{
    const int idx = blockIdx.x * 256 + threadIdx.x;
    const int r = idx >> 10, c = idx & 1023;
    const int base = c & ~15, p = c & 15;
    const int g = p & 3, j = (p >> 2) ^ (r & 3);
    g_xr[idx] = to_tf32(x[(r << 10) + base + (g << 2) + j]);
}

__global__ __launch_bounds__(256)
void prep_wt(const float* __restrict__ Wq, const float* __restrict__ Wk,
             const float* __restrict__ Wv, const float* __restrict__ Wo)
{
    __shared__ float t[32][33];
    const int slot = blockIdx.z;
    const float* w = (slot == 0) ? Wq : (slot == 1) ? Wk : (slot == 2) ? Wv : Wo;
    const int tx = threadIdx.x & 31, ty = threadIdx.x >> 5;  // 32 x 8
    const int n0 = blockIdx.x * 32, k0 = blockIdx.y * 32;
#pragma unroll
    for (int i = 0; i < 4; i++)
        t[ty + 8 * i][tx] = w[(size_t)(k0 + ty + 8 * i) * DMODEL + n0 + tx];
    __syncthreads();
    float* dst = g_wt + (size_t)slot * DMODEL * D_IN;
#pragma unroll
    for (int i = 0; i < 4; i++) {
        const int n = n0 + ty + 8 * i;
        const int kk = tx;
        const int pos = (kk & 16) | (4 * ((kk & 3) ^ (n & 3))) | ((kk >> 2) & 3);
        dst[(size_t)n * D_IN + k0 + pos] = to_tf32(t[kk][ty + 8 * i]);
    }
}

// ---------------------------------------------------------------------------
// TF32 GEMM, cp.async 4-stage (unchanged from round 11).
// ---------------------------------------------------------------------------
#define GS      4
#define G_ST    (128*16)
#define GEMM_SMEM ((2*GS*G_ST) * 4)           // 65536 B

__global__ __launch_bounds__(256, 2)
void gemm_tc(const float* __restrict__ bias,
             float* __restrict__ outp,
             int mode)
{
    extern __shared__ float smg[];
    float* As = smg;
    float* Bs = smg + GS * G_ST;

    const int tid  = threadIdx.x;
    const int lane = tid & 31;
    const int warp = tid >> 5;
    const int wm   = warp >> 2;
    const int wn   = warp & 3;
    const int qr   = lane >> 2;
    const int qi   = lane & 3;
    const int bx   = blockIdx.x;
    const int by   = blockIdx.y;
    const int z    = blockIdx.z;

    const float* A = (mode == 0) ? g_xr : g_ctx;
    const float* Bt = g_wt + (size_t)((mode == 0) ? z : 3) * DMODEL * D_IN;
    const float* Abase = A + (size_t)by * 128 * D_IN;
    const float* Bbase = Bt + (size_t)(bx * 128) * D_IN;

    const int aR0 = tid >> 2,         aC0 = (tid & 3) * 4;
    const int aR1 = (tid + 256) >> 2, aC1 = aC0;

    const uint32_t sA = (uint32_t)__cvta_generic_to_shared(As);
    const uint32_t sB = (uint32_t)__cvta_generic_to_shared(Bs);

    float c[4][4][4];
#pragma unroll
    for (int mf = 0; mf < 4; mf++)
#pragma unroll
        for (int nf = 0; nf < 4; nf++)
#pragma unroll
            for (int k = 0; k < 4; k++) c[mf][nf][k] = 0.f;

    auto issue = [&](int kt, int st) {
        const uint32_t a = sA + st * (G_ST * 4);
        cp16(a + (aR0 * 16 + aC0) * 4, Abase + (size_t)aR0 * D_IN + kt * 16 + aC0);
        cp16(a + (aR1 * 16 + aC1) * 4, Abase + (size_t)aR1 * D_IN + kt * 16 + aC1);
        const uint32_t b = sB + st * (G_ST * 4);
        cp16(b + (aR0 * 16 + aC0) * 4, Bbase + (size_t)aR0 * D_IN + kt * 16 + aC0);
        cp16(b + (aR1 * 16 + aC1) * 4, Bbase + (size_t)aR1 * D_IN + kt * 16 + aC1);
    };

    const int KT = D_IN / 16;
#pragma unroll
    for (int s = 0; s < GS - 1; s++) { issue(s, s); CP_COMMIT(); }

    const int aoff = ((qi ^ (qr & 3)) << 2);

    for (int kt = 0; kt < KT; kt++) {
        CP_WAIT2();
        __syncthreads();
        const int kn = kt + GS - 1;
        if (kn < KT) issue(kn, kn & (GS - 1));
        CP_COMMIT();

        const float* Ab = As + (kt & (GS - 1)) * G_ST;
        const float* Bb = Bs + (kt & (GS - 1)) * G_ST;

        float4 fal[4], fah[4], fb[4];
#pragma unroll
        for (int mf = 0; mf < 4; mf++) {
            const int r0 = wm * 64 + mf * 16 + qr;
            fal[mf] = *(const float4*)&Ab[r0 * 16 + aoff];
            fah[mf] = *(const float4*)&Ab[(r0 + 8) * 16 + aoff];
        }
#pragma unroll
        for (int nf = 0; nf < 4; nf++) {
            const int n = wn * 32 + nf * 8 + qr;
            fb[nf] = *(const float4*)&Bb[n * 16 + aoff];
        }
#pragma unroll
        for (int ks = 0; ks < 2; ks++)
#pragma unroll
            for (int mf = 0; mf < 4; mf++) {
                const float a0 = ks ? fal[mf].z : fal[mf].x;
                const float a1 = ks ? fah[mf].z : fah[mf].x;
                const float a2 = ks ? fal[mf].w : fal[mf].y;
                const float a3 = ks ? fah[mf].w : fah[mf].y;
#pragma unroll
                for (int nf = 0; nf < 4; nf++)
                    mma_tf32(c[mf][nf], a0, a1, a2, a3,
                             ks ? fb[nf].z : fb[nf].x, ks ? fb[nf].w : fb[nf].y);
            }
    }

    if (mode == 0) {
#pragma unroll
        for (int mf = 0; mf < 4; mf++)
#pragma unroll
            for (int nf = 0; nf < 4; nf++)
#pragma unroll
                for (int ci = 0; ci < 4; ci++) {
                    const int m   = by * 128 + wm * 64 + mf * 16 + qr + ((ci >= 2) ? 8 : 0);
                    const int col = bx * 128 + wn * 32 + nf * 8 + 2 * qi + (ci & 1);
                    const int b_ = m >> 11, n_ = m & (NN - 1);
                    const int h_ = col >> 6, d = col & (HD - 1);
                    if (z == 2) {
                        const int nl = n_ & 15;
                        const int np = (n_ & ~15) | (4 * ((nl & 3) ^ (d & 3))) | (nl >> 2);
                        g_v[((size_t)(b_ * NH + h_) * HD + d) * NN + np] = to_tf32(c[mf][nf][ci]);
                    } else {
                        const float mult = (z == 0) ? (0.125f * 1.44269504088896f) : 1.f;
                        const int dl = d & 15, gg = dl >> 2, j = dl & 3;
                        const int dd = (d & ~15) | ((j ^ (n_ & 3)) << 2) | gg;
                        float* O = (z == 0) ? g_q : g_k;
                        O[(((size_t)(b_ * NH + h_)) * NN + n_) * HD + dd] =
                            to_tf32(c[mf][nf][ci] * mult);
                    }
                }
    } else {
#pragma unroll
        for (int mf = 0; mf < 4; mf++)
#pragma unroll
            for (int nf = 0; nf < 4; nf++)
#pragma unroll
                for (int ci = 0; ci < 4; ci++) {
                    const int m   = by * 128 + wm * 64 + mf * 16 + qr + ((ci >= 2) ? 8 : 0);
                    const int col = bx * 128 + wn * 32 + nf * 8 + 2 * qi + (ci & 1);
                    outp[(size_t)m * DMODEL + col] = c[mf][nf][ci] + bias[col];
                }
    }
}

// ---------------------------------------------------------------------------
// Flash attention (causal). BR=128: 256 thr = 8 warps x 16 q-rows, BC=64.
// One K/V tile feeds 128 q-rows (traffic per row halved vs BR=64) and
// 16 warps/SM hide the softmax/shuffle chains. Q frags live in registers;
// K and V^T double-buffered via cp.async; all fragment loads LDS.128.
// P permutation done IN PLACE over s[] (keeps regs <= 128 for 2 CTAs/SM).
// ---------------------------------------------------------------------------
#define AT_STRIDE 80
#define ATTN_SMEM ((2*64*AT_STRIDE + 2*64*AT_STRIDE) * 4)   // 81920 B

__global__ __launch_bounds__(256, 2)
void attn_tc()
{
    extern __shared__ float sm[];
    float* Ks = sm;                        // [2][64 tok][80]
    float* Vs = sm + 2 * 64 * AT_STRIDE;   // [2][64 d][80] (V^T, n-permuted)

    const int tid  = threadIdx.x;
    const int lane = tid & 31;
    const int w    = tid >> 5;             // 0..7
    const int qr   = lane >> 2;
    const int qi   = lane & 3;
    const int qt   = 15 - blockIdx.x;      // longest CTAs first
    const int bh   = blockIdx.y;

    const float* Qg = g_q + ((size_t)bh * NN + qt * 128) * HD;
    const float* Kg = g_k + (size_t)bh * NN * HD;
    const float* Vg = g_v + (size_t)bh * HD * NN;

    const uint32_t sK = (uint32_t)__cvta_generic_to_shared(Ks);
    const uint32_t sV = (uint32_t)__cvta_generic_to_shared(Vs);

    auto issueKV = [&](int kt, int buf) {
        const float* Ktg = Kg + (size_t)kt * 64 * HD;
        const float* Vtg = Vg + kt * 64;
#pragma unroll
        for (int l = 0; l < 4; l++) {
            const int idx = l * 256 + tid;
            const int r = idx >> 4, cc = (idx & 15) * 4;
            cp16(sK + (buf * 64 * AT_STRIDE + r * AT_STRIDE + cc) * 4, Ktg + r * 64 + cc);
            cp16(sV + (buf * 64 * AT_STRIDE + r * AT_STRIDE + cc) * 4, Vtg + (size_t)r * NN + cc);
        }
    };

    issueKV(0, 0);
    CP_COMMIT();

    const int ar   = w * 16 + qr;          // warp-local Q row (0..127)
    const int aoff = ((qi ^ (qr & 3)) << 2);
    const int q2   = (lane & 28) | (qi >> 1);

    // Q fragments for the whole loop: 8 LDG.128 (g_q already fragment-ordered)
    float4 ql[4], qh[4];
#pragma unroll
    for (int cs = 0; cs < 4; cs++) {
        ql[cs] = *(const float4*)(Qg + ar * 64 + cs * 16 + aoff);
        qh[cs] = *(const float4*)(Qg + (ar + 8) * 64 + cs * 16 + aoff);
    }

    float m0 = -1e30f, m1 = -1e30f, l0 = 0.f, l1 = 0.f;
    float o[8][4];
#pragma unroll
    for (int nf = 0; nf < 8; nf++)
#pragma unroll
        for (int ci = 0; ci < 4; ci++) o[nf][ci] = 0.f;

    const int nkt = 2 * qt + 2;
    for (int kt = 0; kt < nkt; kt++) {
        CP_WAIT0();
        __syncthreads();
        if (kt < nkt - 1) issueKV(kt + 1, (kt + 1) & 1);
        CP_COMMIT();

        const float* Kb = Ks + (kt & 1) * 64 * AT_STRIDE;
        const float* Vb = Vs + (kt & 1) * 64 * AT_STRIDE;

        // ---- S = Q K^T ----
        float s[8][4];
#pragma unroll
        for (int nf = 0; nf < 8; nf++)
#pragma unroll
            for (int ci = 0; ci < 4; ci++) s[nf][ci] = 0.f;

#pragma unroll
        for (int cs = 0; cs < 4; cs++) {
#pragma unroll
            for (int nf = 0; nf < 8; nf++) {
                const int kr = nf * 8 + qr;
                const float4 kb = *(const float4*)&Kb[kr * AT_STRIDE + cs * 16 + aoff];
                mma_tf32(s[nf], ql[cs].x, qh[cs].x, ql[cs].y, qh[cs].y, kb.x, kb.y);
                mma_tf32(s[nf], ql[cs].z, qh[cs].z, ql[cs].w, qh[cs].w, kb.z, kb.w);
            }
        }

        // causal mask (only tiles crossing the diagonal: roff < 64)
        const int roff = qt * 128 - kt * 64;
        if (roff < 64) {
            const int r0 = ar + roff, r1 = r0 + 8;
#pragma unroll
            for (int nf = 0; nf < 8; nf++) {
                const int cb = nf * 8 + 2 * qi;
                if (cb     > r0) s[nf][0] = -1e30f;
                if (cb + 1 > r0) s[nf][1] = -1e30f;
                if (cb     > r1) s[nf][2] = -1e30f;
                if (cb + 1 > r1) s[nf][3] = -1e30f;
            }
        }

        // ---- online softmax (base-2, quad reduce) ----
        float mx0 = -1e30f, mx1 = -1e30f;
#pragma unroll
        for (int nf = 0; nf < 8; nf++) {
            mx0 = fmaxf(mx0, fmaxf(s[nf][0], s[nf][1]));
            mx1 = fmaxf(mx1, fmaxf(s[nf][2], s[nf][3]));
        }
        mx0 = fmaxf(mx0, __shfl_xor_sync(0xffffffffu, mx0, 1));
        mx0 = fmaxf(mx0, __shfl_xor_sync(0xffffffffu, mx0, 2));
        mx1 = fmaxf(mx1, __shfl_xor_sync(0xffffffffu, mx1, 1));
        mx1 = fmaxf(mx1, __shfl_xor_sync(0xffffffffu, mx1, 2));

        const float mn0 = fmaxf(m0, mx0), mn1 = fmaxf(m1, mx1);
        const float cf0 = exp2f(m0 - mn0), cf1 = exp2f(m1 - mn1);
        m0 = mn0; m1 = mn1;

        float rs0 = 0.f, rs1 = 0.f;
#pragma unroll
        for (int nf = 0; nf < 8; nf++) {
            s[nf][0] = to_tf32(exp2f(s[nf][0] - mn0)); rs0 += s[nf][0];
            s[nf][1] = to_tf32(exp2f(s[nf][1] - mn0)); rs0 += s[nf][1];
            s[nf][2] = to_tf32(exp2f(s[nf][2] - mn1)); rs1 += s[nf][2];
            s[nf][3] = to_tf32(exp2f(s[nf][3] - mn1)); rs1 += s[nf][3];
        }
        rs0 += __shfl_xor_sync(0xffffffffu, rs0, 1);
        rs0 += __shfl_xor_sync(0xffffffffu, rs0, 2);
        rs1 += __shfl_xor_sync(0xffffffffu, rs1, 1);
        rs1 += __shfl_xor_sync(0xffffffffu, rs1, 2);
        l0 = l0 * cf0 + rs0;
        l1 = l1 * cf1 + rs1;
#pragma unroll
        for (int nf = 0; nf < 8; nf++) {
            o[nf][0] *= cf0; o[nf][1] *= cf0;
            o[nf][2] *= cf1; o[nf][3] *= cf1;
        }

        // ---- P: C-frag -> A-frag via quad shuffles, IN PLACE over s ----
#pragma unroll
        for (int t = 0; t < 8; t++) {
            const float u0 = __shfl_sync(0xffffffffu, s[t][0], q2);
            const float u1 = __shfl_sync(0xffffffffu, s[t][1], q2);
            const float u2 = __shfl_sync(0xffffffffu, s[t][2], q2);
            const float u3 = __shfl_sync(0xffffffffu, s[t][3], q2);
            const float w0 = __shfl_sync(0xffffffffu, s[t][0], q2 + 2);
            const float w1 = __shfl_sync(0xffffffffu, s[t][1], q2 + 2);
            const float w2 = __shfl_sync(0xffffffffu, s[t][2], q2 + 2);
            const float w3 = __shfl_sync(0xffffffffu, s[t][3], q2 + 2);
            const bool hi = (qi & 1);
            s[t][0] = hi ? u1 : u0;
            s[t][1] = hi ? u3 : u2;
            s[t][2] = hi ? w1 : w0;
            s[t][3] = hi ? w3 : w2;
        }

        // ---- O += P V : V^T fragments are LDS.128 (2 k-steps each) ----
#pragma unroll
        for (int cs = 0; cs < 4; cs++) {
#pragma unroll
            for (int nf = 0; nf < 8; nf++) {
                const int dr = nf * 8 + qr;
                const float4 vb = *(const float4*)&Vb[dr * AT_STRIDE + cs * 16 + aoff];
                mma_tf32(o[nf], s[2*cs][0], s[2*cs][1], s[2*cs][2], s[2*cs][3], vb.x, vb.y);
                mma_tf32(o[nf], s[2*cs+1][0], s[2*cs+1][1], s[2*cs+1][2], s[2*cs+1][3], vb.z, vb.w);
            }
        }
    }

    // ---- normalize + write ctx (tf32, k-permuted for out-proj A side) ----
    const int b_ = bh >> 4, h_ = bh & 15;
    const int xkey = qr & 3;
    const float inv0 = 1.f / l0, inv1 = 1.f / l1;
#pragma unroll
    for (int nf = 0; nf < 8; nf++) {
        const int n0 = qt * 128 + ar;
        const int cb = h_ * 64 + nf * 8 + 2 * qi;
        const int cl = cb & 15, gg = cl >> 2, j0 = cl & 3;
        const int c0 = (cb & ~15) | ((j0 ^ xkey) << 2) | gg;
        const int c1 = (cb & ~15) | (((j0 + 1) ^ xkey) << 2) | gg;
        const size_t row0 = (size_t)(b_ * NN + n0) * DMODEL;
        const size_t row1 = (size_t)(b_ * NN + n0 + 8) * DMODEL;
        g_ctx[row0 + c0] = to_tf32(o[nf][0] * inv0);
        g_ctx[row0 + c1] = to_tf32(o[nf][1] * inv0);
        g_ctx[row1 + c0] = to_tf32(o[nf][2] * inv1);
        g_ctx[row1 + c1] = to_tf32(o[nf][3] * inv1);
    }
}

// ---------------------------------------------------------------------------
extern "C" void kernel_launch(void* const* d_in, const int* in_sizes, int n_in,
                              void* d_out, int out_size)
{
    const float* x  = (const float*)d_in[0];
    const float* Wq = (const float*)d_in[1];
    const float* Wk = (const float*)d_in[2];
    const float* Wv = (const float*)d_in[3];
    const float* Wo = (const float*)d_in[4];
    const float* bo = (const float*)d_in[5];
    float* out = (float*)d_out;

    cudaFuncSetAttribute(gemm_tc, cudaFuncAttributeMaxDynamicSharedMemorySize, GEMM_SMEM);
    cudaFuncSetAttribute(attn_tc, cudaFuncAttributeMaxDynamicSharedMemorySize, ATTN_SMEM);

    // one-time tf32 rounding + layout transforms
    prep_x<<<(MTOT * D_IN) / 256, 256>>>(x);
    prep_wt<<<dim3(DMODEL / 32, D_IN / 32, 4), 256>>>(Wq, Wk, Wv, Wo);

    // QKV projections -> g_q/g_k (frag layout), g_v (transposed)
    gemm_tc<<<dim3(8, 64, 3), 256, GEMM_SMEM>>>(nullptr, nullptr, 0);
    // causal flash attention (BR=128)
    attn_tc<<<dim3(16, 64), 256, ATTN_SMEM>>>();
    // output projection + bias
    gemm_tc<<<dim3(8, 64, 1), 256, GEMM_SMEM>>>(bo, out, 1);
}

// round 14
// speedup vs baseline: 1.3336x; 1.3336x over previous
#include <cuda_runtime.h>
#include <cuda_fp16.h>
#include <cstdint>

#define D_IN   1024
#define DMODEL 1024
#define BB     4
#define NN     2048
#define NH     16
#define HD     64
#define MTOT   (BB*NN)   // 8192

// Scratch (device globals; all fp16 pair-permuted layouts)
__device__ __half2 g_xh[(size_t)MTOT*512];        // X [row][512 pairs permuted]
__device__ __half2 g_wh[(size_t)4*DMODEL*512];    // W^T [n][512 pairs permuted]
__device__ __half2 g_qh[(size_t)BB*NH*NN*32];     // Q [bh][n][32 d-pairs permuted], scaled
__device__ __half2 g_kh[(size_t)BB*NH*NN*32];     // K [bh][n][32 d-pairs permuted]
__device__ __half2 g_vh[(size_t)BB*NH*HD*1024];   // V^T [bh][d][1024 tok-pairs permuted]
__device__ __half2 g_ch[(size_t)MTOT*512];        // ctx [row][512 pairs permuted]

// pair-permutation within a 16-pair (32-half) chunk:
// original pair (blk = jl>>3, j = jl&7) -> pos = (j&3)*4 + 2*blk + (j>>2)
// so thread qi's uint4 at byte qi*16 = pairs {(b0,qi),(b0,qi+4),(b1,qi),(b1,qi+4)}
__device__ __forceinline__ int pair_pos(int jl) {
    const int blk = jl >> 3, j = jl & 7;
    return (j & 3) * 4 + 2 * blk + (j >> 2);
}

// D(16x8) += A(16x16,row) * B(16x8,col), fp16 operands packed, fp32 accum
__device__ __forceinline__ void mma_f16(float c[4], uint32_t a0, uint32_t a1,
                                        uint32_t a2, uint32_t a3,
                                        uint32_t b0, uint32_t b1) {
    asm("mma.sync.aligned.m16n8k16.row.col.f32.f16.f16.f32 "
        "{%0,%1,%2,%3},{%4,%5,%6,%7},{%8,%9},{%0,%1,%2,%3};"
        : "+f"(c[0]), "+f"(c[1]), "+f"(c[2]), "+f"(c[3])
        : "r"(a0), "r"(a1), "r"(a2), "r"(a3), "r"(b0), "r"(b1));
}

__device__ __forceinline__ void cp16(uint32_t s, const void* g) {
    asm volatile("cp.async.cg.shared.global [%0], [%1], 16;" :: "r"(s), "l"(g) : "memory");
}
#define CP_COMMIT() asm volatile("cp.async.commit_group;" ::: "memory")

__device__ __forceinline__ uint32_t h2bits(__half2 h) {
    return *reinterpret_cast<uint32_t*>(&h);
}

// ---------------------------------------------------------------------------
// Prep: fp16 conversion + pair permutation. X direct; W transposed to [n][k].
// ---------------------------------------------------------------------------
__global__ __launch_bounds__(256)
void prep_x(const float* __restrict__ x)
{
    const int idx = blockIdx.x * 256 + threadIdx.x;     // global pair index
    const int r = idx >> 9, p = idx & 511;
    const float2 v = *(const float2*)(x + (size_t)r * 1024 + p * 2);
    g_xh[(size_t)r * 512 + (p >> 4) * 16 + pair_pos(p & 15)] = __floats2half2_rn(v.x, v.y);
}

__global__ __launch_bounds__(256)
void prep_wt(const float* __restrict__ Wq, const float* __restrict__ Wk,
             const float* __restrict__ Wv, const float* __restrict__ Wo)
{
    __shared__ float t[32][33];
    const int slot = blockIdx.z;
    const float* w = (slot == 0) ? Wq : (slot == 1) ? Wk : (slot == 2) ? Wv : Wo;
    const int tx = threadIdx.x & 31, ty = threadIdx.x >> 5;
    const int n0 = blockIdx.x * 32, k0 = blockIdx.y * 32;
#pragma unroll
    for (int i = 0; i < 4; i++)       // t[k_local][n_local]
        t[ty + 8 * i][tx] = w[(size_t)(k0 + ty + 8 * i) * DMODEL + n0 + tx];
    __syncthreads();
    const int nl = threadIdx.x >> 3;
    __half2* dst = g_wh + (size_t)slot * DMODEL * 512;
#pragma unroll
    for (int it = 0; it < 2; it++) {
        const int kp = (threadIdx.x & 7) + 8 * it;      // pair within chunk (0..15)
        dst[(size_t)(n0 + nl) * 512 + blockIdx.y * 16 + pair_pos(kp)] =
            __floats2half2_rn(t[2 * kp][nl], t[2 * kp + 1][nl]);
    }
}

// ---------------------------------------------------------------------------
// FP16 GEMM (m16n8k16). CTA 128x128, 8 warps (2m x 4n), warp 64x32. K-tile =
// 32 halves (64B rows -> consecutive rows in disjoint bank halves: all
// fragment loads are conflict-free LDS.128, no padding). cp.async 4-stage.
// mode 0: A=g_xh, B=g_wh[z] -> g_qh/g_kh (frag layout) / g_vh (transposed)
// mode 1: A=g_ch, B=g_wh[3], out = A@W + bias (fp32)
// ---------------------------------------------------------------------------
#define GS 4
#define STAGE_BYTES 16384                 // A 8KB + B 8KB
#define GEMM_SMEM (GS*STAGE_BYTES)        // 65536

__global__ __launch_bounds__(256, 2)
void gemm_f16(const float* __restrict__ bias,
              float* __restrict__ outp,
              int mode)
{
    extern __shared__ char smg[];
    const uint32_t sbase = (uint32_t)__cvta_generic_to_shared(smg);

    const int tid  = threadIdx.x;
    const int lane = tid & 31;
    const int warp = tid >> 5;
    const int wm   = warp >> 2;
    const int wn   = warp & 3;
    const int qr   = lane >> 2;
    const int qi   = lane & 3;
    const int bx   = blockIdx.x;
    const int by   = blockIdx.y;
    const int z    = blockIdx.z;

    const __half* A  = (mode == 0) ? (const __half*)g_xh : (const __half*)g_ch;
    const __half* Bt = (const __half*)g_wh + (size_t)((mode == 0) ? z : 3) * DMODEL * 1024;
    const __half* Abase = A + (size_t)by * 128 * 1024;
    const __half* Bbase = Bt + (size_t)bx * 128 * 1024;

    const int r0 = tid >> 2, c0 = tid & 3;
    const int r1 = (tid + 256) >> 2;

    auto issue = [&](int kt) {
        const uint32_t base = sbase + (kt & 3) * STAGE_BYTES;
        cp16(base + r0 * 64 + c0 * 16,        Abase + (size_t)r0 * 1024 + kt * 32 + c0 * 8);
        cp16(base + r1 * 64 + c0 * 16,        Abase + (size_t)r1 * 1024 + kt * 32 + c0 * 8);
        cp16(base + 8192 + r0 * 64 + c0 * 16, Bbase + (size_t)r0 * 1024 + kt * 32 + c0 * 8);
        cp16(base + 8192 + r1 * 64 + c0 * 16, Bbase + (size_t)r1 * 1024 + kt * 32 + c0 * 8);
    };

    float c[4][4][4];
#pragma unroll
    for (int mf = 0; mf < 4; mf++)
#pragma unroll
        for (int nf = 0; nf < 4; nf++)
#pragma unroll
            for (int k = 0; k < 4; k++) c[mf][nf][k] = 0.f;

    issue(0); CP_COMMIT();
    issue(1); CP_COMMIT();
    issue(2); CP_COMMIT();

    const int KT = 1024 / 32;   // 32
    for (int kt = 0; kt < KT; kt++) {
        asm volatile("cp.async.wait_group 2;" ::: "memory");
        __syncthreads();
        if (kt + 3 < KT) issue(kt + 3);
        CP_COMMIT();

        const char* stg = smg + (kt & 3) * STAGE_BYTES;

        uint4 fa0[4], fa1[4], fb[4];
#pragma unroll
        for (int mf = 0; mf < 4; mf++) {
            const int rr = wm * 64 + mf * 16 + qr;
            fa0[mf] = *(const uint4*)(stg + rr * 64 + qi * 16);
            fa1[mf] = *(const uint4*)(stg + (rr + 8) * 64 + qi * 16);
        }
#pragma unroll
        for (int nf = 0; nf < 4; nf++) {
            const int n = wn * 32 + nf * 8 + qr;
            fb[nf] = *(const uint4*)(stg + 8192 + n * 64 + qi * 16);
        }
#pragma unroll
        for (int mf = 0; mf < 4; mf++)
#pragma unroll
            for (int nf = 0; nf < 4; nf++) {
                mma_f16(c[mf][nf], fa0[mf].x, fa1[mf].x, fa0[mf].y, fa1[mf].y,
                        fb[nf].x, fb[nf].y);
                mma_f16(c[mf][nf], fa0[mf].z, fa1[mf].z, fa0[mf].w, fa1[mf].w,
                        fb[nf].z, fb[nf].w);
            }
    }

    // ---- epilogue (thread owns col pair 2qi,2qi+1 of each nf block) ----
    if (mode == 0) {
        const float mult = (z == 0) ? (0.125f * 1.44269504088896f) : 1.f;
#pragma unroll
        for (int mf = 0; mf < 4; mf++)
#pragma unroll
            for (int nf = 0; nf < 4; nf++) {
                const int mlo = by * 128 + wm * 64 + mf * 16 + qr;
                const int col = bx * 128 + wn * 32 + nf * 8 + 2 * qi;   // even
                const int h_ = col >> 6, d = col & 63;
                if (z == 2) {
                    // V^T [bh][d][tok-pairs permuted]: scalar half stores
                    __half* vb = (__half*)g_vh;
#pragma unroll
                    for (int rs = 0; rs < 2; rs++) {
                        const int m = mlo + 8 * rs;
                        const int b_ = m >> 11, n_ = m & (NN - 1);
                        const int tp = n_ >> 1;
                        const int hidx = (tp >> 4) * 32 + pair_pos(tp & 15) * 2 + (n_ & 1);
                        const size_t rowb = ((size_t)(b_ * NH + h_) * HD);
                        vb[(rowb + d) * 2048 + hidx]     = __float2half_rn(c[mf][nf][2 * rs + 0]);
                        vb[(rowb + d + 1) * 2048 + hidx] = __float2half_rn(c[mf][nf][2 * rs + 1]);
                    }
                } else {
                    __half2* O = (z == 0) ? g_qh : g_kh;
                    const int dp = d >> 1;
                    const int offs = (dp >> 4) * 16 + pair_pos(dp & 15);
#pragma unroll
                    for (int rs = 0; rs < 2; rs++) {
                        const int m = mlo + 8 * rs;
                        const int b_ = m >> 11, n_ = m & (NN - 1);
                        O[(((size_t)(b_ * NH + h_)) * NN + n_) * 32 + offs] =
                            __floats2half2_rn(c[mf][nf][2 * rs] * mult,
                                              c[mf][nf][2 * rs + 1] * mult);
                    }
                }
            }
    } else {
#pragma unroll
        for (int mf = 0; mf < 4; mf++)
#pragma unroll
            for (int nf = 0; nf < 4; nf++) {
                const int mlo = by * 128 + wm * 64 + mf * 16 + qr;
                const int col = bx * 128 + wn * 32 + nf * 8 + 2 * qi;
                const float2 bv = *(const float2*)(bias + col);
#pragma unroll
                for (int rs = 0; rs < 2; rs++) {
                    const int m = mlo + 8 * rs;
                    float2 ov;
                    ov.x = c[mf][nf][2 * rs] + bv.x;
                    ov.y = c[mf][nf][2 * rs + 1] + bv.y;
                    *(float2*)(outp + (size_t)m * DMODEL + col) = ov;
                }
            }
    }
}

// ---------------------------------------------------------------------------
// Flash attention (causal), fp16 m16n8k16. BR=64: 128 thr = 4 warps x 16 rows.
// K/V^T tiles double-buffered via cp.async, stored as 2 sub-tiles of 64B rows
// (conflict-free LDS.128, zero padding). Q frags in registers for the whole
// loop. P C-frag == A-frag when packed to half2: NO shuffles. l sums ROUNDED
// P for exact softmax consistency. 32KB static smem.
// ---------------------------------------------------------------------------
__global__ __launch_bounds__(128, 3)
void attn_f16()
{
    __shared__ char sm[32768];   // K: [2 buf][2 cs][64 tok][64B] ; V at +16384

    const int tid  = threadIdx.x;
    const int lane = tid & 31;
    const int w    = tid >> 5;
    const int qr   = lane >> 2;
    const int qi   = lane & 3;
    const int qt   = 31 - blockIdx.x;      // longest CTAs first
    const int bh   = blockIdx.y;

    const __half* Qg = (const __half*)g_qh + ((size_t)bh * NN + qt * 64) * 64;
    const __half* Kg = (const __half*)g_kh + (size_t)bh * NN * 64;
    const __half* Vg = (const __half*)g_vh + (size_t)bh * HD * 2048;

    const uint32_t sK = (uint32_t)__cvta_generic_to_shared(sm);

    auto issueKV = [&](int kt, int buf) {
#pragma unroll
        for (int l = 0; l < 4; l++) {
            const int idx = l * 128 + tid;
            const int r = idx >> 3, u = idx & 7;         // r: token (K) or d (V)
            const int cs = u >> 2, cc = u & 3;
            cp16(sK + buf * 8192 + cs * 4096 + r * 64 + cc * 16,
                 Kg + (size_t)(kt * 64 + r) * 64 + u * 8);
            cp16(sK + 16384 + buf * 8192 + cs * 4096 + r * 64 + cc * 16,
                 Vg + (size_t)r * 2048 + (kt * 2 + cs) * 32 + cc * 8);
        }
    };

    issueKV(0, 0);
    CP_COMMIT();

    const int ar = w * 16 + qr;

    // Q fragments for the whole loop: 4 LDG.128
    uint4 ql[2], qh_[2];
#pragma unroll
    for (int cs = 0; cs < 2; cs++) {
        ql[cs]  = *(const uint4*)(Qg + ar * 64 + cs * 32 + qi * 8);
        qh_[cs] = *(const uint4*)(Qg + (ar + 8) * 64 + cs * 32 + qi * 8);
    }

    float m0 = -1e30f, m1 = -1e30f, l0 = 0.f, l1 = 0.f;
    float o[8][4];
#pragma unroll
    for (int nf = 0; nf < 8; nf++)
#pragma unroll
        for (int ci = 0; ci < 4; ci++) o[nf][ci] = 0.f;

    for (int kt = 0; kt <= qt; kt++) {
        asm volatile("cp.async.wait_group 0;" ::: "memory");
        __syncthreads();
        if (kt < qt) issueKV(kt + 1, (kt + 1) & 1);
        CP_COMMIT();

        const char* Kb = sm + (kt & 1) * 8192;
        const char* Vb = sm + 16384 + (kt & 1) * 8192;

        // ---- S = Q K^T (4 k16-steps over d=64) ----
        float s[8][4];
#pragma unroll
        for (int nf = 0; nf < 8; nf++)
#pragma unroll
            for (int ci = 0; ci < 4; ci++) s[nf][ci] = 0.f;

#pragma unroll
        for (int cs = 0; cs < 2; cs++) {
#pragma unroll
            for (int nf = 0; nf < 8; nf++) {
                const int kr = nf * 8 + qr;
                const uint4 kb = *(const uint4*)(Kb + cs * 4096 + kr * 64 + qi * 16);
                mma_f16(s[nf], ql[cs].x, qh_[cs].x, ql[cs].y, qh_[cs].y, kb.x, kb.y);
                mma_f16(s[nf], ql[cs].z, qh_[cs].z, ql[cs].w, qh_[cs].w, kb.z, kb.w);
            }
        }

        // causal mask on diagonal tile
        if (kt == qt) {
            const int rr0 = ar, rr1 = ar + 8;
#pragma unroll
            for (int nf = 0; nf < 8; nf++) {
                const int cb = nf * 8 + 2 * qi;
                if (cb     > rr0) s[nf][0] = -1e30f;
                if (cb + 1 > rr0) s[nf][1] = -1e30f;
                if (cb     > rr1) s[nf][2] = -1e30f;
                if (cb + 1 > rr1) s[nf][3] = -1e30f;
            }
        }

        // ---- online softmax (base-2, quad reduce) ----
        float mx0 = -1e30f, mx1 = -1e30f;
#pragma unroll
        for (int nf = 0; nf < 8; nf++) {
            mx0 = fmaxf(mx0, fmaxf(s[nf][0], s[nf][1]));
            mx1 = fmaxf(mx1, fmaxf(s[nf][2], s[nf][3]));
        }
        mx0 = fmaxf(mx0, __shfl_xor_sync(0xffffffffu, mx0, 1));
        mx0 = fmaxf(mx0, __shfl_xor_sync(0xffffffffu, mx0, 2));
        mx1 = fmaxf(mx1, __shfl_xor_sync(0xffffffffu, mx1, 1));
        mx1 = fmaxf(mx1, __shfl_xor_sync(0xffffffffu, mx1, 2));

        const float mn0 = fmaxf(m0, mx0), mn1 = fmaxf(m1, mx1);
        const float cf0 = exp2f(m0 - mn0), cf1 = exp2f(m1 - mn1);
        m0 = mn0; m1 = mn1;

        // ---- P -> fp16 (rounded sums keep l consistent with PV) ----
        uint32_t plo[8], phi[8];
        float rs0 = 0.f, rs1 = 0.f;
#pragma unroll
        for (int nf = 0; nf < 8; nf++) {
            const __half2 h0 = __floats2half2_rn(exp2f(s[nf][0] - mn0),
                                                 exp2f(s[nf][1] - mn0));
            const __half2 h1 = __floats2half2_rn(exp2f(s[nf][2] - mn1),
                                                 exp2f(s[nf][3] - mn1));
            const float2 f0 = __half22float2(h0), f1 = __half22float2(h1);
            rs0 += f0.x + f0.y;
            rs1 += f1.x + f1.y;
            plo[nf] = h2bits(h0);
            phi[nf] = h2bits(h1);
        }
        rs0 += __shfl_xor_sync(0xffffffffu, rs0, 1);
        rs0 += __shfl_xor_sync(0xffffffffu, rs0, 2);
        rs1 += __shfl_xor_sync(0xffffffffu, rs1, 1);
        rs1 += __shfl_xor_sync(0xffffffffu, rs1, 2);
        l0 = l0 * cf0 + rs0;
        l1 = l1 * cf1 + rs1;
#pragma unroll
        for (int nf = 0; nf < 8; nf++) {
            o[nf][0] *= cf0; o[nf][1] *= cf0;
            o[nf][2] *= cf1; o[nf][3] *= cf1;
        }

        // ---- O += P V (P C-frag IS the A-frag; V^T frags are LDS.128) ----
#pragma unroll
        for (int cs = 0; cs < 2; cs++) {
            const int t0 = 2 * cs, t1 = 2 * cs + 1;
#pragma unroll
            for (int nf = 0; nf < 8; nf++) {
                const int dr = nf * 8 + qr;
                const uint4 vb = *(const uint4*)(Vb + cs * 4096 + dr * 64 + qi * 16);
                mma_f16(o[nf], plo[2 * t0], phi[2 * t0], plo[2 * t0 + 1], phi[2 * t0 + 1],
                        vb.x, vb.y);
                mma_f16(o[nf], plo[2 * t1], phi[2 * t1], plo[2 * t1 + 1], phi[2 * t1 + 1],
                        vb.z, vb.w);
            }
        }
    }

    // ---- normalize + write ctx (fp16 pair-permuted for out-proj) ----
    const int b_ = bh >> 4, h_ = bh & 15;
    const float inv0 = 1.f / l0, inv1 = 1.f / l1;
#pragma unroll
    for (int nf = 0; nf < 8; nf++) {
        const int n0 = qt * 64 + ar;
        const int cb = h_ * 64 + nf * 8 + 2 * qi;   // even
        const int p  = cb >> 1;
        const int offs = (p >> 4) * 16 + pair_pos(p & 15);
        g_ch[(size_t)(b_ * NN + n0) * 512 + offs] =
            __floats2half2_rn(o[nf][0] * inv0, o[nf][1] * inv0);
        g_ch[(size_t)(b_ * NN + n0 + 8) * 512 + offs] =
            __floats2half2_rn(o[nf][2] * inv1, o[nf][3] * inv1);
    }
}

// ---------------------------------------------------------------------------
extern "C" void kernel_launch(void* const* d_in, const int* in_sizes, int n_in,
                              void* d_out, int out_size)
{
    const float* x  = (const float*)d_in[0];
    const float* Wq = (const float*)d_in[1];
    const float* Wk = (const float*)d_in[2];
    const float* Wv = (const float*)d_in[3];
    const float* Wo = (const float*)d_in[4];
    const float* bo = (const float*)d_in[5];
    float* out = (float*)d_out;

    cudaFuncSetAttribute(gemm_f16, cudaFuncAttributeMaxDynamicSharedMemorySize, GEMM_SMEM);

    // one-time fp16 conversion + layout transforms
    prep_x<<<(MTOT * 512) / 256, 256>>>(x);
    prep_wt<<<dim3(DMODEL / 32, D_IN / 32, 4), 256>>>(Wq, Wk, Wv, Wo);

    // QKV projections -> g_qh/g_kh (frag layout), g_vh (transposed)
    gemm_f16<<<dim3(8, 64, 3), 256, GEMM_SMEM>>>(nullptr, nullptr, 0);
    // causal flash attention
    attn_f16<<<dim3(32, 64), 128>>>();
    // output projection + bias
    gemm_f16<<<dim3(8, 64, 1), 256, GEMM_SMEM>>>(bo, out, 1);
}

// round 15
// speedup vs baseline: 2.0498x; 1.5371x over previous
#include <cuda_runtime.h>
#include <cuda_fp16.h>
#include <cstdint>

#define D_IN   1024
#define DMODEL 1024
#define BB     4
#define NN     2048
#define NH     16
#define HD     64
#define MTOT   (BB*NN)   // 8192

// Scratch (device globals; all fp16 pair-permuted layouts)
__device__ __half2 g_xh[(size_t)MTOT*512];        // X [row][512 pairs permuted]
__device__ __half2 g_wh[(size_t)4*DMODEL*512];    // W^T [n][512 pairs permuted]
__device__ __half2 g_qh[(size_t)BB*NH*NN*32];     // Q [bh][n][32 d-pairs permuted], scaled
__device__ __half2 g_kh[(size_t)BB*NH*NN*32];     // K [bh][n][32 d-pairs permuted]
__device__ __half2 g_vh[(size_t)BB*NH*HD*1024];   // V^T [bh][d][1024 tok-pairs permuted]
__device__ __half2 g_ch[(size_t)MTOT*512];        // ctx [row][512 pairs permuted]

// pair-permutation within a 16-pair (32-half) chunk:
// original pair (blk = jl>>3, j = jl&7) -> pos = (j&3)*4 + 2*blk + (j>>2)
__device__ __forceinline__ int pair_pos(int jl) {
    const int blk = jl >> 3, j = jl & 7;
    return (j & 3) * 4 + 2 * blk + (j >> 2);
}

__device__ __forceinline__ void mma_f16(float c[4], uint32_t a0, uint32_t a1,
                                        uint32_t a2, uint32_t a3,
                                        uint32_t b0, uint32_t b1) {
    asm("mma.sync.aligned.m16n8k16.row.col.f32.f16.f16.f32 "
        "{%0,%1,%2,%3},{%4,%5,%6,%7},{%8,%9},{%0,%1,%2,%3};"
        : "+f"(c[0]), "+f"(c[1]), "+f"(c[2]), "+f"(c[3])
        : "r"(a0), "r"(a1), "r"(a2), "r"(a3), "r"(b0), "r"(b1));
}

__device__ __forceinline__ void cp16(uint32_t s, const void* g) {
    asm volatile("cp.async.cg.shared.global [%0], [%1], 16;" :: "r"(s), "l"(g) : "memory");
}
#define CP_COMMIT() asm volatile("cp.async.commit_group;" ::: "memory")

__device__ __forceinline__ uint32_t h2bits(__half2 h) {
    return *reinterpret_cast<uint32_t*>(&h);
}

// ---------------------------------------------------------------------------
// Prep: fp16 conversion + pair permutation. X direct; W transposed to [n][k].
// ---------------------------------------------------------------------------
__global__ __launch_bounds__(256)
void prep_x(const float* __restrict__ x)
{
    const int idx = blockIdx.x * 256 + threadIdx.x;     // global pair index
    const int r = idx >> 9, p = idx & 511;
    const float2 v = *(const float2*)(x + (size_t)r * 1024 + p * 2);
    g_xh[(size_t)r * 512 + (p >> 4) * 16 + pair_pos(p & 15)] = __floats2half2_rn(v.x, v.y);
}

__global__ __launch_bounds__(256)
void prep_wt(const float* __restrict__ Wq, const float* __restrict__ Wk,
             const float* __restrict__ Wv, const float* __restrict__ Wo)
{
    __shared__ float t[32][33];
    const int slot = blockIdx.z;
    const float* w = (slot == 0) ? Wq : (slot == 1) ? Wk : (slot == 2) ? Wv : Wo;
    const int tx = threadIdx.x & 31, ty = threadIdx.x >> 5;
    const int n0 = blockIdx.x * 32, k0 = blockIdx.y * 32;
#pragma unroll
    for (int i = 0; i < 4; i++)       // t[k_local][n_local]
        t[ty + 8 * i][tx] = w[(size_t)(k0 + ty + 8 * i) * DMODEL + n0 + tx];
    __syncthreads();
    const int nl = threadIdx.x >> 3;
    __half2* dst = g_wh + (size_t)slot * DMODEL * 512;
#pragma unroll
    for (int it = 0; it < 2; it++) {
        const int kp = (threadIdx.x & 7) + 8 * it;      // pair within chunk (0..15)
        dst[(size_t)(n0 + nl) * 512 + blockIdx.y * 16 + pair_pos(kp)] =
            __floats2half2_rn(t[2 * kp][nl], t[2 * kp + 1][nl]);
    }
}

// ---------------------------------------------------------------------------
// FP16 GEMM (m16n8k16). CTA 128x128, 8 warps (2m x 4n), warp 64x32.
// K-tile = 64 halves stored as TWO stacked 64B-row sub-tiles (keeps the
// conflict-free LDS.128 pattern). 3 cp.async stages x 32KB, wait_group 1,
// ONE barrier per 64-k-halves (half the syncs of r14, 2x the MMA window).
// mode 0: A=g_xh, B=g_wh[z] -> g_qh/g_kh (frag layout) / g_vh (transposed)
// mode 1: A=g_ch, B=g_wh[3], out = A@W + bias (fp32)
// ---------------------------------------------------------------------------
#define GS 3
#define STAGE_BYTES 32768                 // A 16KB + B 16KB, each [2][128][64B]
#define GEMM_SMEM (GS*STAGE_BYTES)        // 98304

__global__ __launch_bounds__(256, 2)
void gemm_f16(const float* __restrict__ bias,
              float* __restrict__ outp,
              int mode)
{
    extern __shared__ char smg[];
    const uint32_t sbase = (uint32_t)__cvta_generic_to_shared(smg);

    const int tid  = threadIdx.x;
    const int lane = tid & 31;
    const int warp = tid >> 5;
    const int wm   = warp >> 2;
    const int wn   = warp & 3;
    const int qr   = lane >> 2;
    const int qi   = lane & 3;
    const int bx   = blockIdx.x;
    const int by   = blockIdx.y;
    const int z    = blockIdx.z;

    const __half* A  = (mode == 0) ? (const __half*)g_xh : (const __half*)g_ch;
    const __half* Bt = (const __half*)g_wh + (size_t)((mode == 0) ? z : 3) * DMODEL * 1024;
    const __half* Abase = A + (size_t)by * 128 * 1024;
    const __half* Bbase = Bt + (size_t)bx * 128 * 1024;

    // per-stage: A 1024 chunks + B 1024 chunks of 16B; 8 chunks/thread
    auto issue = [&](int kt) {
        const uint32_t base = sbase + (kt % GS) * STAGE_BYTES;
#pragma unroll
        for (int l = 0; l < 4; l++) {
            const int idx = l * 256 + tid;
            const int r = idx >> 3, u = idx & 7;
            const int cs = u >> 2, cc = u & 3;
            cp16(base + cs * 8192 + r * 64 + cc * 16,
                 Abase + (size_t)r * 1024 + kt * 64 + u * 8);
            cp16(base + 16384 + cs * 8192 + r * 64 + cc * 16,
                 Bbase + (size_t)r * 1024 + kt * 64 + u * 8);
        }
    };

    float c[4][4][4];
#pragma unroll
    for (int mf = 0; mf < 4; mf++)
#pragma unroll
        for (int nf = 0; nf < 4; nf++)
#pragma unroll
            for (int k = 0; k < 4; k++) c[mf][nf][k] = 0.f;

    issue(0); CP_COMMIT();
    issue(1); CP_COMMIT();

    const int KT = 1024 / 64;   // 16
    for (int kt = 0; kt < KT; kt++) {
        asm volatile("cp.async.wait_group 1;" ::: "memory");
        __syncthreads();
        if (kt + 2 < KT) issue(kt + 2);
        CP_COMMIT();

        const char* stg = smg + (kt % GS) * STAGE_BYTES;

#pragma unroll
        for (int cs = 0; cs < 2; cs++) {
            const char* As = stg + cs * 8192;
            const char* Bs = stg + 16384 + cs * 8192;
            uint4 fa0[4], fa1[4], fb[4];
#pragma unroll
            for (int mf = 0; mf < 4; mf++) {
                const int rr = wm * 64 + mf * 16 + qr;
                fa0[mf] = *(const uint4*)(As + rr * 64 + qi * 16);
                fa1[mf] = *(const uint4*)(As + (rr + 8) * 64 + qi * 16);
            }
#pragma unroll
            for (int nf = 0; nf < 4; nf++) {
                const int n = wn * 32 + nf * 8 + qr;
                fb[nf] = *(const uint4*)(Bs + n * 64 + qi * 16);
            }
#pragma unroll
            for (int mf = 0; mf < 4; mf++)
#pragma unroll
                for (int nf = 0; nf < 4; nf++) {
                    mma_f16(c[mf][nf], fa0[mf].x, fa1[mf].x, fa0[mf].y, fa1[mf].y,
                            fb[nf].x, fb[nf].y);
                    mma_f16(c[mf][nf], fa0[mf].z, fa1[mf].z, fa0[mf].w, fa1[mf].w,
                            fb[nf].z, fb[nf].w);
                }
        }
    }

    // ---- epilogue (thread owns col pair 2qi,2qi+1 of each nf block) ----
    if (mode == 0) {
        const float mult = (z == 0) ? (0.125f * 1.44269504088896f) : 1.f;
#pragma unroll
        for (int mf = 0; mf < 4; mf++)
#pragma unroll
            for (int nf = 0; nf < 4; nf++) {
                const int mlo = by * 128 + wm * 64 + mf * 16 + qr;
                const int col = bx * 128 + wn * 32 + nf * 8 + 2 * qi;   // even
                const int h_ = col >> 6, d = col & 63;
                if (z == 2) {
                    __half* vb = (__half*)g_vh;
#pragma unroll
                    for (int rs = 0; rs < 2; rs++) {
                        const int m = mlo + 8 * rs;
                        const int b_ = m >> 11, n_ = m & (NN - 1);
                        const int tp = n_ >> 1;
                        const int hidx = (tp >> 4) * 32 + pair_pos(tp & 15) * 2 + (n_ & 1);
                        const size_t rowb = ((size_t)(b_ * NH + h_) * HD);
                        vb[(rowb + d) * 2048 + hidx]     = __float2half_rn(c[mf][nf][2 * rs + 0]);
                        vb[(rowb + d + 1) * 2048 + hidx] = __float2half_rn(c[mf][nf][2 * rs + 1]);
                    }
                } else {
                    __half2* O = (z == 0) ? g_qh : g_kh;
                    const int dp = d >> 1;
                    const int offs = (dp >> 4) * 16 + pair_pos(dp & 15);
#pragma unroll
                    for (int rs = 0; rs < 2; rs++) {
                        const int m = mlo + 8 * rs;
                        const int b_ = m >> 11, n_ = m & (NN - 1);
                        O[(((size_t)(b_ * NH + h_)) * NN + n_) * 32 + offs] =
                            __floats2half2_rn(c[mf][nf][2 * rs] * mult,
                                              c[mf][nf][2 * rs + 1] * mult);
                    }
                }
            }
    } else {
#pragma unroll
        for (int mf = 0; mf < 4; mf++)
#pragma unroll
            for (int nf = 0; nf < 4; nf++) {
                const int mlo = by * 128 + wm * 64 + mf * 16 + qr;
                const int col = bx * 128 + wn * 32 + nf * 8 + 2 * qi;
                const float2 bv = *(const float2*)(bias + col);
#pragma unroll
                for (int rs = 0; rs < 2; rs++) {
                    const int m = mlo + 8 * rs;
                    float2 ov;
                    ov.x = c[mf][nf][2 * rs] + bv.x;
                    ov.y = c[mf][nf][2 * rs + 1] + bv.y;
                    *(float2*)(outp + (size_t)m * DMODEL + col) = ov;
                }
            }
    }
}

// ---------------------------------------------------------------------------
// Flash attention (causal), fp16 m16n8k16. BR=64: 128 thr = 4 warps x 16 rows.
// Same math as r14; __launch_bounds__(128,4) caps regs at 128 -> 4 CTAs/SM
// (16 warps/SM) to hide the serial softmax chains. 32KB static smem.
// ---------------------------------------------------------------------------
__global__ __launch_bounds__(128, 4)
void attn_f16()
{
    __shared__ char sm[32768];   // K: [2 buf][2 cs][64 tok][64B] ; V at +16384

    const int tid  = threadIdx.x;
    const int lane = tid & 31;
    const int w    = tid >> 5;
    const int qr   = lane >> 2;
    const int qi   = lane & 3;
    const int qt   = 31 - blockIdx.x;      // longest CTAs first
    const int bh   = blockIdx.y;

    const __half* Qg = (const __half*)g_qh + ((size_t)bh * NN + qt * 64) * 64;
    const __half* Kg = (const __half*)g_kh + (size_t)bh * NN * 64;
    const __half* Vg = (const __half*)g_vh + (size_t)bh * HD * 2048;

    const uint32_t sK = (uint32_t)__cvta_generic_to_shared(sm);

    auto issueKV = [&](int kt, int buf) {
#pragma unroll
        for (int l = 0; l < 4; l++) {
            const int idx = l * 128 + tid;
            const int r = idx >> 3, u = idx & 7;         // r: token (K) or d (V)
            const int cs = u >> 2, cc = u & 3;
            cp16(sK + buf * 8192 + cs * 4096 + r * 64 + cc * 16,
                 Kg + (size_t)(kt * 64 + r) * 64 + u * 8);
            cp16(sK + 16384 + buf * 8192 + cs * 4096 + r * 64 + cc * 16,
                 Vg + (size_t)r * 2048 + (kt * 2 + cs) * 32 + cc * 8);
        }
    };

    issueKV(0, 0);
    CP_COMMIT();

    const int ar = w * 16 + qr;

    // Q fragments for the whole loop: 4 LDG.128
    uint4 ql[2], qh_[2];
#pragma unroll
    for (int cs = 0; cs < 2; cs++) {
        ql[cs]  = *(const uint4*)(Qg + ar * 64 + cs * 32 + qi * 8);
        qh_[cs] = *(const uint4*)(Qg + (ar + 8) * 64 + cs * 32 + qi * 8);
    }

    float m0 = -1e30f, m1 = -1e30f, l0 = 0.f, l1 = 0.f;
    float o[8][4];
#pragma unroll
    for (int nf = 0; nf < 8; nf++)
#pragma unroll
        for (int ci = 0; ci < 4; ci++) o[nf][ci] = 0.f;

    for (int kt = 0; kt <= qt; kt++) {
        asm volatile("cp.async.wait_group 0;" ::: "memory");
        __syncthreads();
        if (kt < qt) issueKV(kt + 1, (kt + 1) & 1);
        CP_COMMIT();

        const char* Kb = sm + (kt & 1) * 8192;
        const char* Vb = sm + 16384 + (kt & 1) * 8192;

        // ---- S = Q K^T (4 k16-steps over d=64) ----
        float s[8][4];
#pragma unroll
        for (int nf = 0; nf < 8; nf++)
#pragma unroll
            for (int ci = 0; ci < 4; ci++) s[nf][ci] = 0.f;

#pragma unroll
        for (int cs = 0; cs < 2; cs++) {
#pragma unroll
            for (int nf = 0; nf < 8; nf++) {
                const int kr = nf * 8 + qr;
                const uint4 kb = *(const uint4*)(Kb + cs * 4096 + kr * 64 + qi * 16);
                mma_f16(s[nf], ql[cs].x, qh_[cs].x, ql[cs].y, qh_[cs].y, kb.x, kb.y);
                mma_f16(s[nf], ql[cs].z, qh_[cs].z, ql[cs].w, qh_[cs].w, kb.z, kb.w);
            }
        }

        // causal mask on diagonal tile
        if (kt == qt) {
            const int rr0 = ar, rr1 = ar + 8;
#pragma unroll
            for (int nf = 0; nf < 8; nf++) {
                const int cb = nf * 8 + 2 * qi;
                if (cb     > rr0) s[nf][0] = -1e30f;
                if (cb + 1 > rr0) s[nf][1] = -1e30f;
                if (cb     > rr1) s[nf][2] = -1e30f;
                if (cb + 1 > rr1) s[nf][3] = -1e30f;
            }
        }

        // ---- online softmax (base-2, quad reduce) ----
        float mx0 = -1e30f, mx1 = -1e30f;
#pragma unroll
        for (int nf = 0; nf < 8; nf++) {
            mx0 = fmaxf(mx0, fmaxf(s[nf][0], s[nf][1]));
            mx1 = fmaxf(mx1, fmaxf(s[nf][2], s[nf][3]));
        }
        mx0 = fmaxf(mx0, __shfl_xor_sync(0xffffffffu, mx0, 1));
        mx0 = fmaxf(mx0, __shfl_xor_sync(0xffffffffu, mx0, 2));
        mx1 = fmaxf(mx1, __shfl_xor_sync(0xffffffffu, mx1, 1));
        mx1 = fmaxf(mx1, __shfl_xor_sync(0xffffffffu, mx1, 2));

        const float mn0 = fmaxf(m0, mx0), mn1 = fmaxf(m1, mx1);
        const float cf0 = exp2f(m0 - mn0), cf1 = exp2f(m1 - mn1);
        m0 = mn0; m1 = mn1;

        // ---- P -> fp16 (rounded sums keep l consistent with PV) ----
        uint32_t plo[8], phi[8];
        float rs0 = 0.f, rs1 = 0.f;
#pragma unroll
        for (int nf = 0; nf < 8; nf++) {
            const __half2 h0 = __floats2half2_rn(exp2f(s[nf][0] - mn0),
                                                 exp2f(s[nf][1] - mn0));
            const __half2 h1 = __floats2half2_rn(exp2f(s[nf][2] - mn1),
                                                 exp2f(s[nf][3] - mn1));
            const float2 f0 = __half22float2(h0), f1 = __half22float2(h1);
            rs0 += f0.x + f0.y;
            rs1 += f1.x + f1.y;
            plo[nf] = h2bits(h0);
            phi[nf] = h2bits(h1);
        }
        rs0 += __shfl_xor_sync(0xffffffffu, rs0, 1);
        rs0 += __shfl_xor_sync(0xffffffffu, rs0, 2);
        rs1 += __shfl_xor_sync(0xffffffffu, rs1, 1);
        rs1 += __shfl_xor_sync(0xffffffffu, rs1, 2);
        l0 = l0 * cf0 + rs0;
        l1 = l1 * cf1 + rs1;
#pragma unroll
        for (int nf = 0; nf < 8; nf++) {
            o[nf][0] *= cf0; o[nf][1] *= cf0;
            o[nf][2] *= cf1; o[nf][3] *= cf1;
        }

        // ---- O += P V (P C-frag IS the A-frag; V^T frags are LDS.128) ----
#pragma unroll
        for (int cs = 0; cs < 2; cs++) {
            const int t0 = 2 * cs, t1 = 2 * cs + 1;
#pragma unroll
            for (int nf = 0; nf < 8; nf++) {
                const int dr = nf * 8 + qr;
                const uint4 vb = *(const uint4*)(Vb + cs * 4096 + dr * 64 + qi * 16);
                mma_f16(o[nf], plo[2 * t0], phi[2 * t0], plo[2 * t0 + 1], phi[2 * t0 + 1],
                        vb.x, vb.y);
                mma_f16(o[nf], plo[2 * t1], phi[2 * t1], plo[2 * t1 + 1], phi[2 * t1 + 1],
                        vb.z, vb.w);
            }
        }
    }

    // ---- normalize + write ctx (fp16 pair-permuted for out-proj) ----
    const int b_ = bh >> 4, h_ = bh & 15;
    const float inv0 = 1.f / l0, inv1 = 1.f / l1;
#pragma unroll
    for (int nf = 0; nf < 8; nf++) {
        const int n0 = qt * 64 + ar;
        const int cb = h_ * 64 + nf * 8 + 2 * qi;   // even
        const int p  = cb >> 1;
        const int offs = (p >> 4) * 16 + pair_pos(p & 15);
        g_ch[(size_t)(b_ * NN + n0) * 512 + offs] =
            __floats2half2_rn(o[nf][0] * inv0, o[nf][1] * inv0);
        g_ch[(size_t)(b_ * NN + n0 + 8) * 512 + offs] =
            __floats2half2_rn(o[nf][2] * inv1, o[nf][3] * inv1);
    }
}

// ---------------------------------------------------------------------------
extern "C" void kernel_launch(void* const* d_in, const int* in_sizes, int n_in,
                              void* d_out, int out_size)
{
    const float* x  = (const float*)d_in[0];
    const float* Wq = (const float*)d_in[1];
    const float* Wk = (const float*)d_in[2];
    const float* Wv = (const float*)d_in[3];
    const float* Wo = (const float*)d_in[4];
    const float* bo = (const float*)d_in[5];
    float* out = (float*)d_out;

    cudaFuncSetAttribute(gemm_f16, cudaFuncAttributeMaxDynamicSharedMemorySize, GEMM_SMEM);

    // one-time fp16 conversion + layout transforms
    prep_x<<<(MTOT * 512) / 256, 256>>>(x);
    prep_wt<<<dim3(DMODEL / 32, D_IN / 32, 4), 256>>>(Wq, Wk, Wv, Wo);

    // QKV projections -> g_qh/g_kh (frag layout), g_vh (transposed)
    gemm_f16<<<dim3(8, 64, 3), 256, GEMM_SMEM>>>(nullptr, nullptr, 0);
    // causal flash attention
    attn_f16<<<dim3(32, 64), 128>>>();
    // output projection + bias
    gemm_f16<<<dim3(8, 64, 1), 256, GEMM_SMEM>>>(bo, out, 1);
}